// round 12
// baseline (speedup 1.0000x reference)
#include <cuda_runtime.h>
#include <cuda_bf16.h>
#include <cstdint>

// Problem constants (fixed by the dataset)
#define NN 50000
#define DH 128
#define EE 800000
#define KK 256

// ---------------------------------------------------------------------------
// Scratch device globals. Referenced ONLY from device code (host-shadow bug!).
// A-side operands and weights stored k-PAIR-PERMUTED (see permk) so LDS.64
// yields the (k, k+4) mma fragment pair. Weights n-major: g_WB[mode][n][k];
// mode blocks contiguous, so [WB0|WB1] and [WB2|WB3] are each one 256n x 256k.
// g_ybf: y = xc@W_l stored bf16 (halves gather traffic).
// ---------------------------------------------------------------------------
__device__ uint32_t g_x32 [NN * DH];
__device__ uint32_t g_h32 [NN * DH];
__device__ uint32_t g_rh32[NN * DH];
__device__ uint32_t g_WB  [4 * KK * DH];
__device__ float g_z  [NN * DH];
__device__ __nv_bfloat16 g_ybf[NN * DH];
__device__ float g_w  [NN * DH];
// CSR for gather
__device__ int g_deg[NN];
__device__ int g_cur[NN];
__device__ int g_off[NN];
__device__ int g_csr[EE];

__device__ __forceinline__ float sigmoidf_(float v) {
    return 1.0f / (1.0f + __expf(-v));
}
__device__ __forceinline__ uint32_t f2tf32(float f) {
    uint32_t r;
    asm("cvt.rna.tf32.f32 %0, %1;" : "=r"(r) : "f"(f));
    return r;
}
__device__ __forceinline__ int permk(int k) {
    return (k & ~15) | (k & 8) | ((k & 3) << 1) | ((k >> 2) & 1);
}
__device__ __forceinline__ void cpasync16(uint32_t dst, const void* src, int sz) {
    asm volatile("cp.async.ca.shared.global [%0], [%1], 16, %2;"
                 :: "r"(dst), "l"(src), "r"(sz));
}
__device__ __forceinline__ void mma_tf32(float c[4], uint32_t a0, uint32_t a1,
                                         uint32_t a2, uint32_t a3,
                                         uint32_t b0, uint32_t b1) {
    asm volatile(
        "mma.sync.aligned.m16n8k8.row.col.f32.tf32.tf32.f32 "
        "{%0,%1,%2,%3}, {%4,%5,%6,%7}, {%8,%9}, {%0,%1,%2,%3};"
        : "+f"(c[0]), "+f"(c[1]), "+f"(c[2]), "+f"(c[3])
        : "r"(a0), "r"(a1), "r"(a2), "r"(a3), "r"(b0), "r"(b1));
}

// ---------------------------------------------------------------------------
// Prep W: transpose to [mode][n][k_perm] tf32 via smem tile.
// ---------------------------------------------------------------------------
__global__ void prep_w(
    const float* __restrict__ W_xr, const float* __restrict__ W_hr,
    const float* __restrict__ W_xz, const float* __restrict__ W_hz,
    const float* __restrict__ W_l,  const float* __restrict__ W_r)
{
    __shared__ float s[32][33];
    const int kb = blockIdx.x, nb = blockIdx.y, mode = blockIdx.z;
    const int tx = threadIdx.x, ty = threadIdx.y;

#pragma unroll
    for (int r = 0; r < 4; r++) {
        const int k = kb * 32 + ty + r * 8;
        const int n = nb * 32 + tx;
        float v;
        if (mode == 0)      v = (k < 128) ? W_xr[k * DH + n] : W_hr[(k - 128) * DH + n];
        else if (mode == 1) v = (k < 128) ? W_xz[k * DH + n] : W_hz[(k - 128) * DH + n];
        else if (mode == 2) v = W_l[k * DH + n];
        else                v = W_r[k * DH + n];
        s[ty + r * 8][tx] = v;
    }
    __syncthreads();
#pragma unroll
    for (int r = 0; r < 4; r++) {
        const int n = nb * 32 + ty + r * 8;
        const int k = kb * 32 + tx;
        g_WB[(size_t)mode * KK * DH + n * KK + permk(k)] = f2tf32(s[tx][ty + r * 8]);
    }
}

// Prep: tf32(x), tf32(h) with k-pair permutation.
__global__ __launch_bounds__(256) void prep_xh(
    const float* __restrict__ x, const float* __restrict__ h)
{
    const int i = blockIdx.x * blockDim.x + threadIdx.x;  // over NN*DH/4
    if (i >= NN * (DH / 4)) return;
    const int node = i >> 5;
    const int k    = (i & 31) * 4;
    const size_t base = (size_t)node * DH;
    const float4 xv = *(const float4*)&x[(size_t)i * 4];
    const float4 hv = *(const float4*)&h[(size_t)i * 4];
    g_x32[base + permk(k + 0)] = f2tf32(xv.x);
    g_x32[base + permk(k + 1)] = f2tf32(xv.y);
    g_x32[base + permk(k + 2)] = f2tf32(xv.z);
    g_x32[base + permk(k + 3)] = f2tf32(xv.w);
    g_h32[base + permk(k + 0)] = f2tf32(hv.x);
    g_h32[base + permk(k + 1)] = f2tf32(hv.y);
    g_h32[base + permk(k + 2)] = f2tf32(hv.z);
    g_h32[base + permk(k + 3)] = f2tf32(hv.w);
}

// ---------------------------------------------------------------------------
// CSR build: zero -> histogram -> single-block scan -> bucket fill
// ---------------------------------------------------------------------------
__global__ __launch_bounds__(256) void zero_dc()
{
    const int i = blockIdx.x * blockDim.x + threadIdx.x;
    if (i < NN) { g_deg[i] = 0; g_cur[i] = 0; }
}
__global__ __launch_bounds__(256) void hist_kernel(const int* __restrict__ ei)
{
    const int i = blockIdx.x * blockDim.x + threadIdx.x;
    if (i < EE) atomicAdd(&g_deg[ei[EE + i]], 1);
}
__global__ __launch_bounds__(1024) void scan_kernel()
{
    __shared__ int part[1024];
    const int t = threadIdx.x;
    const int CH = (NN + 1023) / 1024;   // 49
    const int base = t * CH;
    int s = 0;
    for (int i = 0; i < CH; i++) {
        const int idx = base + i;
        if (idx < NN) s += g_deg[idx];
    }
    part[t] = s;
    __syncthreads();
    for (int d = 1; d < 1024; d <<= 1) {
        int v = (t >= d) ? part[t - d] : 0;
        __syncthreads();
        part[t] += v;
        __syncthreads();
    }
    int run = (t == 0) ? 0 : part[t - 1];
    for (int i = 0; i < CH; i++) {
        const int idx = base + i;
        if (idx < NN) { g_off[idx] = run; run += g_deg[idx]; }
    }
}
__global__ __launch_bounds__(256) void fill_kernel(const int* __restrict__ ei)
{
    const int i = blockIdx.x * blockDim.x + threadIdx.x;
    if (i >= EE) return;
    const int dst = ei[EE + i];
    const int pos = atomicAdd(&g_cur[dst], 1);
    g_csr[g_off[dst] + pos] = ei[i];
}

// ---------------------------------------------------------------------------
// Fused-N TF32 GEMM: C[128, 256] = A[128, 256] @ B[256n, 256k]^T
// 8 warps, 64x64 warp tiles (2m x 4n). 3-stage cp.async, dynamic smem 96KB.
//   GRP 0: A=[x|h],  B=[WB0|WB1]: cols 0-127 -> rh (tf32 permk), 128-255 -> z
//   GRP 1: A=[x|rh], B=[WB2|WB3]: cols 0-127 -> y (bf16),        128-255 -> w
// Crossbar bytes/MAC = 0.168 (vs 0.25 for the 4-launch N=128 version).
// ---------------------------------------------------------------------------
#define AP 24
#define BP 20
#define ST 3
#define A_WORDS (128 * AP)
#define B_WORDS (256 * BP)

template <int GRP>
__global__ __launch_bounds__(256, 1) void gemm_fused(
    const float* __restrict__ bias_r, const float* __restrict__ bias_z,
    const float* __restrict__ hprev, int Nrows)
{
    extern __shared__ uint32_t sm[];
    uint32_t* AsBase = sm;                 // ST * A_WORDS
    uint32_t* BsBase = sm + ST * A_WORDS;  // ST * B_WORDS

    const uint32_t* A0 = g_x32;
    const uint32_t* A1 = (GRP == 1) ? g_rh32 : g_h32;
    const uint32_t* B  = g_WB + (size_t)(GRP * 2) * (KK * DH);  // 256n x 256k

    const int tid  = threadIdx.x;
    const int lane = tid & 31;
    const int wid  = tid >> 5;
    const int row0 = blockIdx.x * 128;
    const int wm   = (wid >> 2) * 64;   // 0 / 64
    const int wn   = (wid & 3) * 64;    // 0/64/128/192
    const int g    = lane >> 2;
    const int t    = lane & 3;

    float acc[4][8][4];
#pragma unroll
    for (int mi = 0; mi < 4; mi++)
#pragma unroll
        for (int ni = 0; ni < 8; ni++)
#pragma unroll
            for (int q = 0; q < 4; q++) acc[mi][ni][q] = 0.0f;

    auto stage = [&](int c, int buf) {
        const int k0 = c * 16;
        const uint32_t* Asrc = (k0 < 128) ? A0 : A1;
        const int ka = k0 & 127;
        uint32_t* As = AsBase + buf * A_WORDS;
        uint32_t* Bs = BsBase + buf * B_WORDS;
#pragma unroll
        for (int i = 0; i < 2; i++) {      // A: 128 rows x 16 words = 512 f4
            const int id  = tid + i * 256;
            const int row = id >> 2;
            const int kq  = (id & 3) * 4;
            const uint32_t dst = (uint32_t)__cvta_generic_to_shared(
                &As[row * AP + kq]);
            const int sz = (row0 + row < Nrows) ? 16 : 0;
            cpasync16(dst, &Asrc[(size_t)(row0 + row) * DH + ka + kq], sz);
        }
#pragma unroll
        for (int i = 0; i < 4; i++) {      // B: 256 n x 16 words = 1024 f4
            const int id = tid + i * 256;
            const int n  = id >> 2;
            const int kq = (id & 3) * 4;
            const uint32_t dst = (uint32_t)__cvta_generic_to_shared(
                &Bs[n * BP + kq]);
            cpasync16(dst, &B[(size_t)n * KK + k0 + kq], 16);
        }
        asm volatile("cp.async.commit_group;");
    };

    stage(0, 0);
    stage(1, 1);

#pragma unroll 1
    for (int c = 0; c < 16; c++) {
        if (c < 15) { asm volatile("cp.async.wait_group 1;"); }
        else        { asm volatile("cp.async.wait_group 0;"); }
        __syncthreads();   // also fences: chunk c-1 reads done -> buf (c+2)%ST free

        if (c + 2 < 16) stage(c + 2, (c + 2) % ST);

        const uint32_t* As = AsBase + (c % ST) * A_WORDS;
        const uint32_t* Bs = BsBase + (c % ST) * B_WORDS;
#pragma unroll
        for (int k8 = 0; k8 < 2; k8++) {
            uint32_t a[4][4], b[8][2];
#pragma unroll
            for (int mi = 0; mi < 4; mi++) {
                const int rb = wm + mi * 16 + g;
                const uint2 lo = *(const uint2*)&As[rb * AP + k8 * 8 + 2 * t];
                const uint2 hi = *(const uint2*)&As[(rb + 8) * AP + k8 * 8 + 2 * t];
                a[mi][0] = lo.x; a[mi][1] = hi.x; a[mi][2] = lo.y; a[mi][3] = hi.y;
            }
#pragma unroll
            for (int ni = 0; ni < 8; ni++) {
                const int cb = wn + ni * 8 + g;
                const uint2 v = *(const uint2*)&Bs[cb * BP + k8 * 8 + 2 * t];
                b[ni][0] = v.x; b[ni][1] = v.y;
            }
#pragma unroll
            for (int mi = 0; mi < 4; mi++)
#pragma unroll
                for (int ni = 0; ni < 8; ni++)
                    mma_tf32(acc[mi][ni], a[mi][0], a[mi][1], a[mi][2], a[mi][3],
                             b[ni][0], b[ni][1]);
        }
    }

    // epilogue: thread owns (row = wm+mi*16+g(+8), cols = wn+ni*8+2t, +1)
#pragma unroll
    for (int mi = 0; mi < 4; mi++) {
#pragma unroll
        for (int half = 0; half < 2; half++) {
            const int grow = row0 + wm + mi * 16 + g + half * 8;
            if (grow >= Nrows) continue;
            const size_t rbase = (size_t)grow * DH;
#pragma unroll
            for (int ni = 0; ni < 8; ni++) {
                const int col = wn + ni * 8 + 2 * t;   // 0..255
                float c0 = acc[mi][ni][half * 2 + 0];
                float c1 = acc[mi][ni][half * 2 + 1];
                if (GRP == 0) {
                    if (col < 128) {
                        c0 = sigmoidf_(c0 + bias_r[col]);
                        c1 = sigmoidf_(c1 + bias_r[col + 1]);
                        const float2 hh = *(const float2*)&hprev[rbase + col];
                        g_rh32[rbase + permk(col)]     = f2tf32(c0 * hh.x);
                        g_rh32[rbase + permk(col + 1)] = f2tf32(c1 * hh.y);
                    } else {
                        const int cz = col - 128;
                        float2 o;
                        o.x = sigmoidf_(c0 + bias_z[cz]);
                        o.y = sigmoidf_(c1 + bias_z[cz + 1]);
                        *(float2*)&g_z[rbase + cz] = o;
                    }
                } else {
                    if (col < 128) {
                        __nv_bfloat162 p;
                        p.x = __float2bfloat16_rn(c0);
                        p.y = __float2bfloat16_rn(c1);
                        *(__nv_bfloat162*)&g_ybf[rbase + col] = p;
                    } else {
                        *(float2*)&g_w[rbase + col - 128] = make_float2(c0, c1);
                    }
                }
            }
        }
    }
}

// ---------------------------------------------------------------------------
// Gather + final fused: one warp per node; y rows are bf16 (8B per lane).
// out = (1-z) * (sum_nbr(y)/max(deg,1) + b_l + w) + z * h_prev
// ---------------------------------------------------------------------------
__global__ __launch_bounds__(256) void gather_final(
    const float* __restrict__ hprev, const float* __restrict__ b_l,
    float* __restrict__ out)
{
    const int node = (blockIdx.x * blockDim.x + threadIdx.x) >> 5;
    const int lane = threadIdx.x & 31;
    if (node >= NN) return;

    const int off = g_off[node];
    const int deg = g_deg[node];

    float4 acc = make_float4(0.f, 0.f, 0.f, 0.f);
    auto addrow = [&](int s) {
        const uint2 v = *(const uint2*)&g_ybf[(size_t)s * DH + lane * 4];
        const float2 p0 = __bfloat1622float2(*(const __nv_bfloat162*)&v.x);
        const float2 p1 = __bfloat1622float2(*(const __nv_bfloat162*)&v.y);
        acc.x += p0.x; acc.y += p0.y; acc.z += p1.x; acc.w += p1.y;
    };

    int e = 0;
    for (; e + 4 <= deg; e += 4) {
        const int s0 = g_csr[off + e + 0];
        const int s1 = g_csr[off + e + 1];
        const int s2 = g_csr[off + e + 2];
        const int s3 = g_csr[off + e + 3];
        addrow(s0); addrow(s1); addrow(s2); addrow(s3);
    }
    for (; e < deg; e++) addrow(g_csr[off + e]);

    const float inv = 1.0f / (float)max(deg, 1);
    const size_t o = (size_t)node * DH + lane * 4;
    const float4 w  = *(const float4*)&g_w[o];
    const float4 z  = *(const float4*)&g_z[o];
    const float4 hh = *(const float4*)&hprev[o];
    const float4 bl = *(const float4*)&b_l[lane * 4];

    float4 r;
    float n;
    n = fmaf(acc.x, inv, bl.x) + w.x; r.x = (1.0f - z.x) * n + z.x * hh.x;
    n = fmaf(acc.y, inv, bl.y) + w.y; r.y = (1.0f - z.y) * n + z.y * hh.y;
    n = fmaf(acc.z, inv, bl.z) + w.z; r.z = (1.0f - z.z) * n + z.z * hh.z;
    n = fmaf(acc.w, inv, bl.w) + w.w; r.w = (1.0f - z.w) * n + z.w * hh.w;
    *(float4*)&out[o] = r;
}

// ---------------------------------------------------------------------------
extern "C" void kernel_launch(void* const* d_in, const int* in_sizes, int n_in,
                              void* d_out, int out_size)
{
    const float* x    = (const float*)d_in[0];
    const int*   ei   = (const int*)  d_in[1];
    const float* h    = (const float*)d_in[2];
    const float* W_xr = (const float*)d_in[3];
    const float* b_xr = (const float*)d_in[4];
    const float* W_hr = (const float*)d_in[5];
    const float* W_xz = (const float*)d_in[6];
    const float* b_xz = (const float*)d_in[7];
    const float* W_hz = (const float*)d_in[8];
    const float* W_l  = (const float*)d_in[9];
    const float* b_l  = (const float*)d_in[10];
    const float* W_r  = (const float*)d_in[11];
    float* out = (float*)d_out;

    const int gemm_grid = (NN + 127) / 128;   // 391
    const int SMEM_BYTES = (ST * A_WORDS + ST * B_WORDS) * 4;  // 96KB

    // One-time resources (created on the first, non-captured, call)
    static cudaStream_t sC = nullptr;
    static cudaEvent_t evRoot, evC;
    if (!sC) {
        cudaStreamCreateWithFlags(&sC, cudaStreamNonBlocking);
        cudaEventCreateWithFlags(&evRoot, cudaEventDisableTiming);
        cudaEventCreateWithFlags(&evC,    cudaEventDisableTiming);
        cudaFuncSetAttribute(gemm_fused<0>,
            cudaFuncAttributeMaxDynamicSharedMemorySize, SMEM_BYTES);
        cudaFuncSetAttribute(gemm_fused<1>,
            cudaFuncAttributeMaxDynamicSharedMemorySize, SMEM_BYTES);
    }

    // Fork: CSR build hidden on side stream
    cudaEventRecord(evRoot, 0);
    cudaStreamWaitEvent(sC, evRoot, 0);
    zero_dc<<<(NN + 255) / 256, 256, 0, sC>>>();
    hist_kernel<<<(EE + 255) / 256, 256, 0, sC>>>(ei);
    scan_kernel<<<1, 1024, 0, sC>>>();
    fill_kernel<<<(EE + 255) / 256, 256, 0, sC>>>(ei);
    cudaEventRecord(evC, sC);

    // Main stream: preps -> gates -> candidate
    prep_w<<<dim3(8, 4, 4), dim3(32, 8)>>>(W_xr, W_hr, W_xz, W_hz, W_l, W_r);
    prep_xh<<<(NN * (DH / 4) + 255) / 256, 256>>>(x, h);

    gemm_fused<0><<<gemm_grid, 256, SMEM_BYTES>>>(b_xr, b_xz, h, NN);
    gemm_fused<1><<<gemm_grid, 256, SMEM_BYTES>>>(b_xr, b_xz, h, NN);

    // Join CSR, then fused gather + final
    cudaStreamWaitEvent(0, evC, 0);
    gather_final<<<(NN * 32 + 255) / 256, 256>>>(h, b_l, out);
}

// round 13
// speedup vs baseline: 1.4321x; 1.4321x over previous
#include <cuda_runtime.h>
#include <cuda_bf16.h>
#include <cstdint>

// Problem constants (fixed by the dataset)
#define NN 50000
#define DH 128
#define EE 800000
#define KK 256

// ---------------------------------------------------------------------------
// Scratch device globals. Referenced ONLY from device code (host-shadow bug!).
// x and h_prev are consumed DIRECTLY by the tf32 GEMMs (mma.sync tf32 reads
// the top 19 bits of fp32 => HW truncation; budgeted). rh is stored rna-
// rounded tf32 bits. Weights n-major: g_WB[mode][n][k] (no permutation).
// g_ybf: y = xc@W_l stored bf16 (halves gather traffic).
// ---------------------------------------------------------------------------
__device__ uint32_t g_rh32[NN * DH];
__device__ uint32_t g_WB  [4 * KK * DH];
__device__ float g_z  [NN * DH];
__device__ __nv_bfloat16 g_ybf[NN * DH];
__device__ float g_w  [NN * DH];
__device__ float g_agg[NN * DH];
// CSR for gather
__device__ int g_deg[NN];
__device__ int g_cur[NN];
__device__ int g_off[NN];
__device__ int g_csr[EE];

__device__ __forceinline__ float sigmoidf_(float v) {
    return 1.0f / (1.0f + __expf(-v));
}
__device__ __forceinline__ uint32_t f2tf32(float f) {
    uint32_t r;
    asm("cvt.rna.tf32.f32 %0, %1;" : "=r"(r) : "f"(f));
    return r;
}
__device__ __forceinline__ void cpasync16(uint32_t dst, const void* src, int sz) {
    asm volatile("cp.async.ca.shared.global [%0], [%1], 16, %2;"
                 :: "r"(dst), "l"(src), "r"(sz));
}
__device__ __forceinline__ void mma_tf32(float c[4], uint32_t a0, uint32_t a1,
                                         uint32_t a2, uint32_t a3,
                                         uint32_t b0, uint32_t b1) {
    asm volatile(
        "mma.sync.aligned.m16n8k8.row.col.f32.tf32.tf32.f32 "
        "{%0,%1,%2,%3}, {%4,%5,%6,%7}, {%8,%9}, {%0,%1,%2,%3};"
        : "+f"(c[0]), "+f"(c[1]), "+f"(c[2]), "+f"(c[3])
        : "r"(a0), "r"(a1), "r"(a2), "r"(a3), "r"(b0), "r"(b1));
}

// ---------------------------------------------------------------------------
// Prep W: transpose to [mode][n][k] tf32 (rna) via smem tile. No permutation.
// ---------------------------------------------------------------------------
__global__ void prep_w(
    const float* __restrict__ W_xr, const float* __restrict__ W_hr,
    const float* __restrict__ W_xz, const float* __restrict__ W_hz,
    const float* __restrict__ W_l,  const float* __restrict__ W_r)
{
    __shared__ float s[32][33];
    const int kb = blockIdx.x, nb = blockIdx.y, mode = blockIdx.z;
    const int tx = threadIdx.x, ty = threadIdx.y;

#pragma unroll
    for (int r = 0; r < 4; r++) {
        const int k = kb * 32 + ty + r * 8;
        const int n = nb * 32 + tx;
        float v;
        if (mode == 0)      v = (k < 128) ? W_xr[k * DH + n] : W_hr[(k - 128) * DH + n];
        else if (mode == 1) v = (k < 128) ? W_xz[k * DH + n] : W_hz[(k - 128) * DH + n];
        else if (mode == 2) v = W_l[k * DH + n];
        else                v = W_r[k * DH + n];
        s[ty + r * 8][tx] = v;
    }
    __syncthreads();
#pragma unroll
    for (int r = 0; r < 4; r++) {
        const int n = nb * 32 + ty + r * 8;
        const int k = kb * 32 + tx;
        g_WB[(size_t)mode * KK * DH + n * KK + k] = f2tf32(s[tx][ty + r * 8]);
    }
}

// ---------------------------------------------------------------------------
// CSR build: zero -> histogram -> single-block scan -> bucket fill
// ---------------------------------------------------------------------------
__global__ __launch_bounds__(256) void zero_dc()
{
    const int i = blockIdx.x * blockDim.x + threadIdx.x;
    if (i < NN) { g_deg[i] = 0; g_cur[i] = 0; }
}
__global__ __launch_bounds__(256) void hist_kernel(const int* __restrict__ ei)
{
    const int i = blockIdx.x * blockDim.x + threadIdx.x;
    if (i < EE) atomicAdd(&g_deg[ei[EE + i]], 1);
}
__global__ __launch_bounds__(1024) void scan_kernel()
{
    __shared__ int part[1024];
    const int t = threadIdx.x;
    const int CH = (NN + 1023) / 1024;   // 49
    const int base = t * CH;
    int s = 0;
    for (int i = 0; i < CH; i++) {
        const int idx = base + i;
        if (idx < NN) s += g_deg[idx];
    }
    part[t] = s;
    __syncthreads();
    for (int d = 1; d < 1024; d <<= 1) {
        int v = (t >= d) ? part[t - d] : 0;
        __syncthreads();
        part[t] += v;
        __syncthreads();
    }
    int run = (t == 0) ? 0 : part[t - 1];
    for (int i = 0; i < CH; i++) {
        const int idx = base + i;
        if (idx < NN) { g_off[idx] = run; run += g_deg[idx]; }
    }
}
__global__ __launch_bounds__(256) void fill_kernel(const int* __restrict__ ei)
{
    const int i = blockIdx.x * blockDim.x + threadIdx.x;
    if (i >= EE) return;
    const int dst = ei[EE + i];
    const int pos = atomicAdd(&g_cur[dst], 1);
    g_csr[g_off[dst] + pos] = ei[i];
}

// ---------------------------------------------------------------------------
// TF32 tensor-core GEMM: champion R8/R10 shape (BM=128 BN=128 BK=16, 8 warps
// of 64x32, 3-stage cp.async, one sync per chunk), R5-style LDS.32 fragment
// loads (no layout permutation -> x/h consumed directly from harness bufs).
//   MODE 0: [x|h]  @ WB0 -> rh (tf32 rna bits)
//   MODE 1: [x|h]  @ WB1 -> z
//   MODE 2: [x|rh] @ WB2 -> y (bf16)
//   MODE 3: [x|rh] @ WB3 -> w
// ---------------------------------------------------------------------------
#define AP 20
#define BP 20
#define ST 3

template <int MODE>
__global__ __launch_bounds__(256, 2) void gemm_tf32(
    const uint32_t* __restrict__ xp, const uint32_t* __restrict__ hp,
    const float* __restrict__ bias, const float* __restrict__ hprev, int Nrows)
{
    __shared__ uint32_t As[ST][128 * AP];
    __shared__ uint32_t Bs[ST][128 * BP];

    const uint32_t* A0 = xp;
    const uint32_t* A1 = (MODE >= 2) ? (const uint32_t*)g_rh32 : hp;
    const uint32_t* B  = g_WB + (size_t)MODE * (KK * DH);

    const int tid  = threadIdx.x;
    const int lane = tid & 31;
    const int wid  = tid >> 5;
    const int row0 = blockIdx.x * 128;
    const int wm   = (wid >> 2) * 64;
    const int wn   = (wid & 3) * 32;
    const int g    = lane >> 2;
    const int t    = lane & 3;

    float acc[4][4][4];
#pragma unroll
    for (int mi = 0; mi < 4; mi++)
#pragma unroll
        for (int ni = 0; ni < 4; ni++)
#pragma unroll
            for (int q = 0; q < 4; q++) acc[mi][ni][q] = 0.0f;

    auto stage = [&](int c, int buf) {
        const int k0 = c * 16;
        const uint32_t* Asrc = (k0 < 128) ? A0 : A1;
        const int ka = k0 & 127;
#pragma unroll
        for (int i = 0; i < 2; i++) {      // A: 128 rows x 16 words
            const int id  = tid + i * 256;
            const int row = id >> 2;
            const int kq  = (id & 3) * 4;
            const uint32_t dst = (uint32_t)__cvta_generic_to_shared(
                &As[buf][row * AP + kq]);
            const int sz = (row0 + row < Nrows) ? 16 : 0;
            cpasync16(dst, &Asrc[(size_t)(row0 + row) * DH + ka + kq], sz);
        }
#pragma unroll
        for (int i = 0; i < 2; i++) {      // B: 128 n x 16 words
            const int id = tid + i * 256;
            const int n  = id >> 2;
            const int kq = (id & 3) * 4;
            const uint32_t dst = (uint32_t)__cvta_generic_to_shared(
                &Bs[buf][n * BP + kq]);
            cpasync16(dst, &B[(size_t)n * KK + k0 + kq], 16);
        }
        asm volatile("cp.async.commit_group;");
    };

    stage(0, 0);
    stage(1, 1);

#pragma unroll 1
    for (int c = 0; c < 16; c++) {
        if (c < 15) { asm volatile("cp.async.wait_group 1;"); }
        else        { asm volatile("cp.async.wait_group 0;"); }
        __syncthreads();   // also fences: chunk c-1 reads done -> buf (c+2)%ST free

        if (c + 2 < 16) stage(c + 2, (c + 2) % ST);

        const int buf = c % ST;
#pragma unroll
        for (int k8 = 0; k8 < 2; k8++) {
            const int kk = k8 * 8;
            uint32_t a[4][4], b[4][2];
#pragma unroll
            for (int mi = 0; mi < 4; mi++) {
                const int rb = wm + mi * 16 + g;
                a[mi][0] = As[buf][(rb)     * AP + kk + t];
                a[mi][1] = As[buf][(rb + 8) * AP + kk + t];
                a[mi][2] = As[buf][(rb)     * AP + kk + t + 4];
                a[mi][3] = As[buf][(rb + 8) * AP + kk + t + 4];
            }
#pragma unroll
            for (int ni = 0; ni < 4; ni++) {
                const int cb = wn + ni * 8 + g;
                b[ni][0] = Bs[buf][cb * BP + kk + t];
                b[ni][1] = Bs[buf][cb * BP + kk + t + 4];
            }
#pragma unroll
            for (int mi = 0; mi < 4; mi++)
#pragma unroll
                for (int ni = 0; ni < 4; ni++)
                    mma_tf32(acc[mi][ni], a[mi][0], a[mi][1], a[mi][2], a[mi][3],
                             b[ni][0], b[ni][1]);
        }
    }

    // epilogue: thread owns (row = wm+mi*16+g(+8), cols = wn+ni*8+2t, +1)
#pragma unroll
    for (int mi = 0; mi < 4; mi++) {
#pragma unroll
        for (int half = 0; half < 2; half++) {
            const int grow = row0 + wm + mi * 16 + g + half * 8;
            if (grow >= Nrows) continue;
#pragma unroll
            for (int ni = 0; ni < 4; ni++) {
                const int col = wn + ni * 8 + 2 * t;
                float c0 = acc[mi][ni][half * 2 + 0];
                float c1 = acc[mi][ni][half * 2 + 1];
                const size_t off = (size_t)grow * DH + col;
                if (MODE == 0) {
                    c0 = sigmoidf_(c0 + bias[col]);
                    c1 = sigmoidf_(c1 + bias[col + 1]);
                    const float2 hh = *(const float2*)&hprev[off];
                    uint2 o;
                    o.x = f2tf32(c0 * hh.x);
                    o.y = f2tf32(c1 * hh.y);
                    *(uint2*)&g_rh32[off] = o;
                } else if (MODE == 1) {
                    float2 o;
                    o.x = sigmoidf_(c0 + bias[col]);
                    o.y = sigmoidf_(c1 + bias[col + 1]);
                    *(float2*)&g_z[off] = o;
                } else if (MODE == 2) {
                    __nv_bfloat162 p;
                    p.x = __float2bfloat16_rn(c0);
                    p.y = __float2bfloat16_rn(c1);
                    *(__nv_bfloat162*)&g_ybf[off] = p;
                } else {
                    *(float2*)&g_w[off] = make_float2(c0, c1);
                }
            }
        }
    }
}

// ---------------------------------------------------------------------------
// Gather: one warp per node, sum neighbor y rows (bf16) -> g_agg (fp32).
// Runs on the CSR side-stream, overlapped with the w-GEMM.
// ---------------------------------------------------------------------------
__global__ __launch_bounds__(256) void gather_y()
{
    const int node = (blockIdx.x * blockDim.x + threadIdx.x) >> 5;
    const int lane = threadIdx.x & 31;
    if (node >= NN) return;

    const int off = g_off[node];
    const int deg = g_deg[node];

    float4 acc = make_float4(0.f, 0.f, 0.f, 0.f);
    auto addrow = [&](int s) {
        const uint2 v = *(const uint2*)&g_ybf[(size_t)s * DH + lane * 4];
        const float2 p0 = __bfloat1622float2(*(const __nv_bfloat162*)&v.x);
        const float2 p1 = __bfloat1622float2(*(const __nv_bfloat162*)&v.y);
        acc.x += p0.x; acc.y += p0.y; acc.z += p1.x; acc.w += p1.y;
    };

    int e = 0;
    for (; e + 4 <= deg; e += 4) {
        const int s0 = g_csr[off + e + 0];
        const int s1 = g_csr[off + e + 1];
        const int s2 = g_csr[off + e + 2];
        const int s3 = g_csr[off + e + 3];
        addrow(s0); addrow(s1); addrow(s2); addrow(s3);
    }
    for (; e < deg; e++) addrow(g_csr[off + e]);

    *(float4*)&g_agg[(size_t)node * DH + lane * 4] = acc;
}

// ---------------------------------------------------------------------------
// Final: out = (1-z) * (agg/max(deg,1) + b_l + w) + z * h_prev
// ---------------------------------------------------------------------------
__global__ __launch_bounds__(256) void final_kernel(
    const float* __restrict__ hprev, const float* __restrict__ b_l,
    float* __restrict__ out)
{
    const int i4 = blockIdx.x * blockDim.x + threadIdx.x;   // over NN*32
    if (i4 >= NN * (DH / 4)) return;
    const int node = i4 >> 5;
    const int c4   = i4 & 31;
    const size_t off = (size_t)i4 * 4;

    const float inv = 1.0f / (float)max(g_deg[node], 1);
    const float4 a  = *(const float4*)&g_agg[off];
    const float4 w  = *(const float4*)&g_w[off];
    const float4 z  = *(const float4*)&g_z[off];
    const float4 hh = *(const float4*)&hprev[off];
    const float4 bl = *(const float4*)&b_l[c4 * 4];

    float4 o;
    float n;
    n = fmaf(a.x, inv, bl.x) + w.x; o.x = (1.0f - z.x) * n + z.x * hh.x;
    n = fmaf(a.y, inv, bl.y) + w.y; o.y = (1.0f - z.y) * n + z.y * hh.y;
    n = fmaf(a.z, inv, bl.z) + w.z; o.z = (1.0f - z.z) * n + z.z * hh.z;
    n = fmaf(a.w, inv, bl.w) + w.w; o.w = (1.0f - z.w) * n + z.w * hh.w;
    *(float4*)&out[off] = o;
}

// ---------------------------------------------------------------------------
extern "C" void kernel_launch(void* const* d_in, const int* in_sizes, int n_in,
                              void* d_out, int out_size)
{
    const float* x    = (const float*)d_in[0];
    const int*   ei   = (const int*)  d_in[1];
    const float* h    = (const float*)d_in[2];
    const float* W_xr = (const float*)d_in[3];
    const float* b_xr = (const float*)d_in[4];
    const float* W_hr = (const float*)d_in[5];
    const float* W_xz = (const float*)d_in[6];
    const float* b_xz = (const float*)d_in[7];
    const float* W_hz = (const float*)d_in[8];
    const float* W_l  = (const float*)d_in[9];
    const float* b_l  = (const float*)d_in[10];
    const float* W_r  = (const float*)d_in[11];
    float* out = (float*)d_out;

    const uint32_t* xu = (const uint32_t*)x;
    const uint32_t* hu = (const uint32_t*)h;

    const int gemm_grid = (NN + 127) / 128;   // 391

    // One-time resources (created on the first, non-captured, call)
    static cudaStream_t sB = nullptr, sC = nullptr;
    static cudaEvent_t evRoot, evA, evG2, evB1, evGY;
    if (!sB) {
        cudaStreamCreateWithFlags(&sB, cudaStreamNonBlocking);
        cudaStreamCreateWithFlags(&sC, cudaStreamNonBlocking);
        cudaEventCreateWithFlags(&evRoot, cudaEventDisableTiming);
        cudaEventCreateWithFlags(&evA,    cudaEventDisableTiming);
        cudaEventCreateWithFlags(&evG2,   cudaEventDisableTiming);
        cudaEventCreateWithFlags(&evB1,   cudaEventDisableTiming);
        cudaEventCreateWithFlags(&evGY,   cudaEventDisableTiming);
    }

    // Fork point
    cudaEventRecord(evRoot, 0);

    // --- Stream C: CSR build (independent of GEMMs) ---
    cudaStreamWaitEvent(sC, evRoot, 0);
    zero_dc<<<(NN + 255) / 256, 256, 0, sC>>>();
    hist_kernel<<<(EE + 255) / 256, 256, 0, sC>>>(ei);
    scan_kernel<<<1, 1024, 0, sC>>>();
    fill_kernel<<<(EE + 255) / 256, 256, 0, sC>>>(ei);

    // --- Main stream: weight prep only (x/h consumed directly) ---
    prep_w<<<dim3(8, 4, 4), dim3(32, 8)>>>(W_xr, W_hr, W_xz, W_hz, W_l, W_r);
    cudaEventRecord(evA, 0);

    // --- Stream B: z-gate (independent of r-gate chain) ---
    cudaStreamWaitEvent(sB, evA, 0);
    gemm_tf32<1><<<gemm_grid, 256, 0, sB>>>(xu, hu, b_xz, h, NN);
    cudaEventRecord(evB1, sB);

    // --- Main stream: r-gate -> y ---
    gemm_tf32<0><<<gemm_grid, 256>>>(xu, hu, b_xr, h, NN);
    gemm_tf32<2><<<gemm_grid, 256>>>(xu, hu, nullptr, h, NN);
    cudaEventRecord(evG2, 0);

    // --- Stream C: gather_y (needs y + CSR) — overlaps the w-GEMM ---
    cudaStreamWaitEvent(sC, evG2, 0);
    gather_y<<<(NN * 32 + 255) / 256, 256, 0, sC>>>();
    cudaEventRecord(evGY, sC);

    // --- Main stream: w (needs rh; ordered after r-gate on main) ---
    gemm_tf32<3><<<gemm_grid, 256>>>(xu, hu, nullptr, h, NN);

    // --- Join: final needs w (main), z (sB), agg (sC) ---
    cudaStreamWaitEvent(0, evB1, 0);
    cudaStreamWaitEvent(0, evGY, 0);
    final_kernel<<<(NN * (DH / 4) + 255) / 256, 256>>>(h, b_l, out);
}

// round 14
// speedup vs baseline: 1.4723x; 1.0281x over previous
#include <cuda_runtime.h>
#include <cuda_bf16.h>
#include <cstdint>

// Problem constants (fixed by the dataset)
#define NN 50000
#define DH 128
#define EE 800000
#define KK 256

// ---------------------------------------------------------------------------
// Scratch device globals. Referenced ONLY from device code (host-shadow bug!).
// x and h_prev are consumed DIRECTLY by the tf32 GEMMs (mma.sync tf32 reads
// the top 19 bits of fp32 => HW truncation; budgeted). rh is stored rna-
// rounded tf32 bits. Weights n-major: g_WB[mode][n][k].
// g_ybf: y = xc@W_l stored bf16 (halves gather traffic).
// ---------------------------------------------------------------------------
__device__ uint32_t g_rh32[NN * DH];
__device__ uint32_t g_WB  [4 * KK * DH];
__device__ float g_z  [NN * DH];
__device__ __nv_bfloat16 g_ybf[NN * DH];
__device__ float g_w  [NN * DH];
// CSR for gather
__device__ int g_deg[NN];
__device__ int g_cur[NN];
__device__ int g_off[NN];
__device__ int g_csr[EE];

__device__ __forceinline__ float sigmoidf_(float v) {
    return 1.0f / (1.0f + __expf(-v));
}
__device__ __forceinline__ uint32_t f2tf32(float f) {
    uint32_t r;
    asm("cvt.rna.tf32.f32 %0, %1;" : "=r"(r) : "f"(f));
    return r;
}
__device__ __forceinline__ void cpasync16(uint32_t dst, const void* src, int sz) {
    asm volatile("cp.async.ca.shared.global [%0], [%1], 16, %2;"
                 :: "r"(dst), "l"(src), "r"(sz));
}
__device__ __forceinline__ void mma_tf32(float c[4], uint32_t a0, uint32_t a1,
                                         uint32_t a2, uint32_t a3,
                                         uint32_t b0, uint32_t b1) {
    asm volatile(
        "mma.sync.aligned.m16n8k8.row.col.f32.tf32.tf32.f32 "
        "{%0,%1,%2,%3}, {%4,%5,%6,%7}, {%8,%9}, {%0,%1,%2,%3};"
        : "+f"(c[0]), "+f"(c[1]), "+f"(c[2]), "+f"(c[3])
        : "r"(a0), "r"(a1), "r"(a2), "r"(a3), "r"(b0), "r"(b1));
}

// ---------------------------------------------------------------------------
// Prep W: transpose to [mode][n][k] tf32 (rna) via smem tile.
// ---------------------------------------------------------------------------
__global__ void prep_w(
    const float* __restrict__ W_xr, const float* __restrict__ W_hr,
    const float* __restrict__ W_xz, const float* __restrict__ W_hz,
    const float* __restrict__ W_l,  const float* __restrict__ W_r)
{
    __shared__ float s[32][33];
    const int kb = blockIdx.x, nb = blockIdx.y, mode = blockIdx.z;
    const int tx = threadIdx.x, ty = threadIdx.y;

#pragma unroll
    for (int r = 0; r < 4; r++) {
        const int k = kb * 32 + ty + r * 8;
        const int n = nb * 32 + tx;
        float v;
        if (mode == 0)      v = (k < 128) ? W_xr[k * DH + n] : W_hr[(k - 128) * DH + n];
        else if (mode == 1) v = (k < 128) ? W_xz[k * DH + n] : W_hz[(k - 128) * DH + n];
        else if (mode == 2) v = W_l[k * DH + n];
        else                v = W_r[k * DH + n];
        s[ty + r * 8][tx] = v;
    }
    __syncthreads();
#pragma unroll
    for (int r = 0; r < 4; r++) {
        const int n = nb * 32 + ty + r * 8;
        const int k = kb * 32 + tx;
        g_WB[(size_t)mode * KK * DH + n * KK + k] = f2tf32(s[tx][ty + r * 8]);
    }
}

// ---------------------------------------------------------------------------
// CSR build: zero -> histogram -> single-block scan -> bucket fill
// ---------------------------------------------------------------------------
__global__ __launch_bounds__(256) void zero_dc()
{
    const int i = blockIdx.x * blockDim.x + threadIdx.x;
    if (i < NN) { g_deg[i] = 0; g_cur[i] = 0; }
}
__global__ __launch_bounds__(256) void hist_kernel(const int* __restrict__ ei)
{
    const int i = blockIdx.x * blockDim.x + threadIdx.x;
    if (i < EE) atomicAdd(&g_deg[ei[EE + i]], 1);
}
__global__ __launch_bounds__(1024) void scan_kernel()
{
    __shared__ int part[1024];
    const int t = threadIdx.x;
    const int CH = (NN + 1023) / 1024;   // 49
    const int base = t * CH;
    int s = 0;
    for (int i = 0; i < CH; i++) {
        const int idx = base + i;
        if (idx < NN) s += g_deg[idx];
    }
    part[t] = s;
    __syncthreads();
    for (int d = 1; d < 1024; d <<= 1) {
        int v = (t >= d) ? part[t - d] : 0;
        __syncthreads();
        part[t] += v;
        __syncthreads();
    }
    int run = (t == 0) ? 0 : part[t - 1];
    for (int i = 0; i < CH; i++) {
        const int idx = base + i;
        if (idx < NN) { g_off[idx] = run; run += g_deg[idx]; }
    }
}
__global__ __launch_bounds__(256) void fill_kernel(const int* __restrict__ ei)
{
    const int i = blockIdx.x * blockDim.x + threadIdx.x;
    if (i >= EE) return;
    const int dst = ei[EE + i];
    const int pos = atomicAdd(&g_cur[dst], 1);
    g_csr[g_off[dst] + pos] = ei[i];
}

// ---------------------------------------------------------------------------
// Paired TF32 GEMM: one launch computes TWO GEMMs sharing the same A operand,
// grid (391, 2), blockIdx.y = mode-within-pair. Mainloop is the champion
// shape (BM=128 BN=128 BK=16, 8 warps of 64x32, 3-stage cp.async).
//   PAIR 0 (A=[x|h]):  y=0 -> rh = sigmoid(.+b_xr)*h (tf32 bits)
//                      y=1 -> z  = sigmoid(.+b_xz)
//   PAIR 1 (A=[x|rh]): y=0 -> y (bf16)
//                      y=1 -> w
// Uniform CTA duration within each launch => clean wave packing (6 tau total
// vs 7-8 for sequential/forked schedules).
// ---------------------------------------------------------------------------
#define AP 20
#define BP 20
#define ST 3

template <int PAIR>
__global__ __launch_bounds__(256, 2) void gemm_pair(
    const uint32_t* __restrict__ xp, const uint32_t* __restrict__ hp,
    const float* __restrict__ bias_r, const float* __restrict__ bias_z,
    const float* __restrict__ hprev, int Nrows)
{
    __shared__ uint32_t As[ST][128 * AP];
    __shared__ uint32_t Bs[ST][128 * BP];

    const int ymode = blockIdx.y;                    // 0 or 1 (CTA-uniform)
    const uint32_t* A0 = xp;
    const uint32_t* A1 = (PAIR == 1) ? (const uint32_t*)g_rh32 : hp;
    const uint32_t* B  = g_WB + (size_t)(PAIR * 2 + ymode) * (KK * DH);

    const int tid  = threadIdx.x;
    const int lane = tid & 31;
    const int wid  = tid >> 5;
    const int row0 = blockIdx.x * 128;
    const int wm   = (wid >> 2) * 64;
    const int wn   = (wid & 3) * 32;
    const int g    = lane >> 2;
    const int t    = lane & 3;

    float acc[4][4][4];
#pragma unroll
    for (int mi = 0; mi < 4; mi++)
#pragma unroll
        for (int ni = 0; ni < 4; ni++)
#pragma unroll
            for (int q = 0; q < 4; q++) acc[mi][ni][q] = 0.0f;

    auto stage = [&](int c, int buf) {
        const int k0 = c * 16;
        const uint32_t* Asrc = (k0 < 128) ? A0 : A1;
        const int ka = k0 & 127;
#pragma unroll
        for (int i = 0; i < 2; i++) {      // A: 128 rows x 16 words
            const int id  = tid + i * 256;
            const int row = id >> 2;
            const int kq  = (id & 3) * 4;
            const uint32_t dst = (uint32_t)__cvta_generic_to_shared(
                &As[buf][row * AP + kq]);
            const int sz = (row0 + row < Nrows) ? 16 : 0;
            cpasync16(dst, &Asrc[(size_t)(row0 + row) * DH + ka + kq], sz);
        }
#pragma unroll
        for (int i = 0; i < 2; i++) {      // B: 128 n x 16 words
            const int id = tid + i * 256;
            const int n  = id >> 2;
            const int kq = (id & 3) * 4;
            const uint32_t dst = (uint32_t)__cvta_generic_to_shared(
                &Bs[buf][n * BP + kq]);
            cpasync16(dst, &B[(size_t)n * KK + k0 + kq], 16);
        }
        asm volatile("cp.async.commit_group;");
    };

    stage(0, 0);
    stage(1, 1);

#pragma unroll 1
    for (int c = 0; c < 16; c++) {
        if (c < 15) { asm volatile("cp.async.wait_group 1;"); }
        else        { asm volatile("cp.async.wait_group 0;"); }
        __syncthreads();   // also fences: chunk c-1 reads done -> buf (c+2)%ST free

        if (c + 2 < 16) stage(c + 2, (c + 2) % ST);

        const int buf = c % ST;
#pragma unroll
        for (int k8 = 0; k8 < 2; k8++) {
            const int kk = k8 * 8;
            uint32_t a[4][4], b[4][2];
#pragma unroll
            for (int mi = 0; mi < 4; mi++) {
                const int rb = wm + mi * 16 + g;
                a[mi][0] = As[buf][(rb)     * AP + kk + t];
                a[mi][1] = As[buf][(rb + 8) * AP + kk + t];
                a[mi][2] = As[buf][(rb)     * AP + kk + t + 4];
                a[mi][3] = As[buf][(rb + 8) * AP + kk + t + 4];
            }
#pragma unroll
            for (int ni = 0; ni < 4; ni++) {
                const int cb = wn + ni * 8 + g;
                b[ni][0] = Bs[buf][cb * BP + kk + t];
                b[ni][1] = Bs[buf][cb * BP + kk + t + 4];
            }
#pragma unroll
            for (int mi = 0; mi < 4; mi++)
#pragma unroll
                for (int ni = 0; ni < 4; ni++)
                    mma_tf32(acc[mi][ni], a[mi][0], a[mi][1], a[mi][2], a[mi][3],
                             b[ni][0], b[ni][1]);
        }
    }

    // epilogue: thread owns (row = wm+mi*16+g(+8), cols = wn+ni*8+2t, +1)
#pragma unroll
    for (int mi = 0; mi < 4; mi++) {
#pragma unroll
        for (int half = 0; half < 2; half++) {
            const int grow = row0 + wm + mi * 16 + g + half * 8;
            if (grow >= Nrows) continue;
#pragma unroll
            for (int ni = 0; ni < 4; ni++) {
                const int col = wn + ni * 8 + 2 * t;
                float c0 = acc[mi][ni][half * 2 + 0];
                float c1 = acc[mi][ni][half * 2 + 1];
                const size_t off = (size_t)grow * DH + col;
                if (PAIR == 0) {
                    if (ymode == 0) {
                        c0 = sigmoidf_(c0 + bias_r[col]);
                        c1 = sigmoidf_(c1 + bias_r[col + 1]);
                        const float2 hh = *(const float2*)&hprev[off];
                        uint2 o;
                        o.x = f2tf32(c0 * hh.x);
                        o.y = f2tf32(c1 * hh.y);
                        *(uint2*)&g_rh32[off] = o;
                    } else {
                        float2 o;
                        o.x = sigmoidf_(c0 + bias_z[col]);
                        o.y = sigmoidf_(c1 + bias_z[col + 1]);
                        *(float2*)&g_z[off] = o;
                    }
                } else {
                    if (ymode == 0) {
                        __nv_bfloat162 p;
                        p.x = __float2bfloat16_rn(c0);
                        p.y = __float2bfloat16_rn(c1);
                        *(__nv_bfloat162*)&g_ybf[off] = p;
                    } else {
                        *(float2*)&g_w[off] = make_float2(c0, c1);
                    }
                }
            }
        }
    }
}

// ---------------------------------------------------------------------------
// Gather + final fused: one warp per node; y rows are bf16 (8B per lane).
// out = (1-z) * (sum_nbr(y)/max(deg,1) + b_l + w) + z * h_prev
// ---------------------------------------------------------------------------
__global__ __launch_bounds__(256) void gather_final(
    const float* __restrict__ hprev, const float* __restrict__ b_l,
    float* __restrict__ out)
{
    const int node = (blockIdx.x * blockDim.x + threadIdx.x) >> 5;
    const int lane = threadIdx.x & 31;
    if (node >= NN) return;

    const int off = g_off[node];
    const int deg = g_deg[node];

    float4 acc = make_float4(0.f, 0.f, 0.f, 0.f);
    auto addrow = [&](int s) {
        const uint2 v = *(const uint2*)&g_ybf[(size_t)s * DH + lane * 4];
        const float2 p0 = __bfloat1622float2(*(const __nv_bfloat162*)&v.x);
        const float2 p1 = __bfloat1622float2(*(const __nv_bfloat162*)&v.y);
        acc.x += p0.x; acc.y += p0.y; acc.z += p1.x; acc.w += p1.y;
    };

    int e = 0;
    for (; e + 4 <= deg; e += 4) {
        const int s0 = g_csr[off + e + 0];
        const int s1 = g_csr[off + e + 1];
        const int s2 = g_csr[off + e + 2];
        const int s3 = g_csr[off + e + 3];
        addrow(s0); addrow(s1); addrow(s2); addrow(s3);
    }
    for (; e < deg; e++) addrow(g_csr[off + e]);

    const float inv = 1.0f / (float)max(deg, 1);
    const size_t o = (size_t)node * DH + lane * 4;
    const float4 w  = *(const float4*)&g_w[o];
    const float4 z  = *(const float4*)&g_z[o];
    const float4 hh = *(const float4*)&hprev[o];
    const float4 bl = *(const float4*)&b_l[lane * 4];

    float4 r;
    float n;
    n = fmaf(acc.x, inv, bl.x) + w.x; r.x = (1.0f - z.x) * n + z.x * hh.x;
    n = fmaf(acc.y, inv, bl.y) + w.y; r.y = (1.0f - z.y) * n + z.y * hh.y;
    n = fmaf(acc.z, inv, bl.z) + w.z; r.z = (1.0f - z.z) * n + z.z * hh.z;
    n = fmaf(acc.w, inv, bl.w) + w.w; r.w = (1.0f - z.w) * n + z.w * hh.w;
    *(float4*)&out[o] = r;
}

// ---------------------------------------------------------------------------
extern "C" void kernel_launch(void* const* d_in, const int* in_sizes, int n_in,
                              void* d_out, int out_size)
{
    const float* x    = (const float*)d_in[0];
    const int*   ei   = (const int*)  d_in[1];
    const float* h    = (const float*)d_in[2];
    const float* W_xr = (const float*)d_in[3];
    const float* b_xr = (const float*)d_in[4];
    const float* W_hr = (const float*)d_in[5];
    const float* W_xz = (const float*)d_in[6];
    const float* b_xz = (const float*)d_in[7];
    const float* W_hz = (const float*)d_in[8];
    const float* W_l  = (const float*)d_in[9];
    const float* b_l  = (const float*)d_in[10];
    const float* W_r  = (const float*)d_in[11];
    float* out = (float*)d_out;

    const uint32_t* xu = (const uint32_t*)x;
    const uint32_t* hu = (const uint32_t*)h;

    const int gemm_grid = (NN + 127) / 128;   // 391

    // One-time resources (created on the first, non-captured, call)
    static cudaStream_t sC = nullptr;
    static cudaEvent_t evRoot, evC;
    if (!sC) {
        cudaStreamCreateWithFlags(&sC, cudaStreamNonBlocking);
        cudaEventCreateWithFlags(&evRoot, cudaEventDisableTiming);
        cudaEventCreateWithFlags(&evC,    cudaEventDisableTiming);
    }

    // Fork: CSR build hidden on side stream
    cudaEventRecord(evRoot, 0);
    cudaStreamWaitEvent(sC, evRoot, 0);
    zero_dc<<<(NN + 255) / 256, 256, 0, sC>>>();
    hist_kernel<<<(EE + 255) / 256, 256, 0, sC>>>(ei);
    scan_kernel<<<1, 1024, 0, sC>>>();
    fill_kernel<<<(EE + 255) / 256, 256, 0, sC>>>(ei);
    cudaEventRecord(evC, sC);

    // Main stream: prep -> gates pair -> candidate pair
    prep_w<<<dim3(8, 4, 4), dim3(32, 8)>>>(W_xr, W_hr, W_xz, W_hz, W_l, W_r);
    gemm_pair<0><<<dim3(gemm_grid, 2), 256>>>(xu, hu, b_xr, b_xz, h, NN);
    gemm_pair<1><<<dim3(gemm_grid, 2), 256>>>(xu, hu, b_xr, b_xz, h, NN);

    // Join CSR, then fused gather + final
    cudaStreamWaitEvent(0, evC, 0);
    gather_final<<<(NN * 32 + 255) / 256, 256>>>(h, b_l, out);
}

// round 15
// speedup vs baseline: 1.5644x; 1.0625x over previous
#include <cuda_runtime.h>
#include <cuda_bf16.h>
#include <cstdint>

// Problem constants (fixed by the dataset)
#define NN 50000
#define DH 128
#define EE 800000
#define KK 256

// ---------------------------------------------------------------------------
// Scratch device globals. Referenced ONLY from device code (host-shadow bug!).
// x/h_prev consumed directly by tf32 GEMMs (HW-truncated tf32; budgeted).
// rh stored rna-rounded tf32 bits. Weights n-major: g_WB[mode][n][k].
// g_ybf: y stored bf16 (halves gather traffic).
// g_flag[i]: rh rows [128i,128(i+1)) ready (release/acquire handshake).
// ---------------------------------------------------------------------------
__device__ uint32_t g_rh32[NN * DH];
__device__ uint32_t g_WB  [4 * KK * DH];
__device__ float g_z  [NN * DH];
__device__ __nv_bfloat16 g_ybf[NN * DH];
__device__ float g_w  [NN * DH];
__device__ int g_flag[512];
// CSR for gather
__device__ int g_deg[NN];
__device__ int g_cur[NN];
__device__ int g_off[NN];
__device__ int g_csr[EE];

__device__ __forceinline__ float sigmoidf_(float v) {
    return 1.0f / (1.0f + __expf(-v));
}
__device__ __forceinline__ uint32_t f2tf32(float f) {
    uint32_t r;
    asm("cvt.rna.tf32.f32 %0, %1;" : "=r"(r) : "f"(f));
    return r;
}
__device__ __forceinline__ void cpasync16(uint32_t dst, const void* src, int sz) {
    asm volatile("cp.async.ca.shared.global [%0], [%1], 16, %2;"
                 :: "r"(dst), "l"(src), "r"(sz));
}
__device__ __forceinline__ void mma_tf32(float c[4], uint32_t a0, uint32_t a1,
                                         uint32_t a2, uint32_t a3,
                                         uint32_t b0, uint32_t b1) {
    asm volatile(
        "mma.sync.aligned.m16n8k8.row.col.f32.tf32.tf32.f32 "
        "{%0,%1,%2,%3}, {%4,%5,%6,%7}, {%8,%9}, {%0,%1,%2,%3};"
        : "+f"(c[0]), "+f"(c[1]), "+f"(c[2]), "+f"(c[3])
        : "r"(a0), "r"(a1), "r"(a2), "r"(a3), "r"(b0), "r"(b1));
}

// ---------------------------------------------------------------------------
// Prep W: transpose to [mode][n][k] tf32 (rna) via smem tile.
// Also zeroes g_flag (graph-replay safe: runs on main stream before GEMM).
// ---------------------------------------------------------------------------
__global__ void prep_w(
    const float* __restrict__ W_xr, const float* __restrict__ W_hr,
    const float* __restrict__ W_xz, const float* __restrict__ W_hz,
    const float* __restrict__ W_l,  const float* __restrict__ W_r)
{
    __shared__ float s[32][33];
    const int kb = blockIdx.x, nb = blockIdx.y, mode = blockIdx.z;
    const int tx = threadIdx.x, ty = threadIdx.y;

    // zero rh-ready flags (first 512 global threads)
    if (kb == 0 && nb == 0 && mode == 0) {
        const int t = ty * 32 + tx;
        if (t < 512) g_flag[t] = 0;
    }

#pragma unroll
    for (int r = 0; r < 4; r++) {
        const int k = kb * 32 + ty + r * 8;
        const int n = nb * 32 + tx;
        float v;
        if (mode == 0)      v = (k < 128) ? W_xr[k * DH + n] : W_hr[(k - 128) * DH + n];
        else if (mode == 1) v = (k < 128) ? W_xz[k * DH + n] : W_hz[(k - 128) * DH + n];
        else if (mode == 2) v = W_l[k * DH + n];
        else                v = W_r[k * DH + n];
        s[ty + r * 8][tx] = v;
    }
    __syncthreads();
#pragma unroll
    for (int r = 0; r < 4; r++) {
        const int n = nb * 32 + ty + r * 8;
        const int k = kb * 32 + tx;
        g_WB[(size_t)mode * KK * DH + n * KK + k] = f2tf32(s[tx][ty + r * 8]);
    }
}

// ---------------------------------------------------------------------------
// CSR build: zero -> histogram -> single-block scan -> bucket fill
// ---------------------------------------------------------------------------
__global__ __launch_bounds__(256) void zero_dc()
{
    const int i = blockIdx.x * blockDim.x + threadIdx.x;
    if (i < NN) { g_deg[i] = 0; g_cur[i] = 0; }
}
__global__ __launch_bounds__(256) void hist_kernel(const int* __restrict__ ei)
{
    const int i = blockIdx.x * blockDim.x + threadIdx.x;
    if (i < EE) atomicAdd(&g_deg[ei[EE + i]], 1);
}
__global__ __launch_bounds__(1024) void scan_kernel()
{
    __shared__ int part[1024];
    const int t = threadIdx.x;
    const int CH = (NN + 1023) / 1024;   // 49
    const int base = t * CH;
    int s = 0;
    for (int i = 0; i < CH; i++) {
        const int idx = base + i;
        if (idx < NN) s += g_deg[idx];
    }
    part[t] = s;
    __syncthreads();
    for (int d = 1; d < 1024; d <<= 1) {
        int v = (t >= d) ? part[t - d] : 0;
        __syncthreads();
        part[t] += v;
        __syncthreads();
    }
    int run = (t == 0) ? 0 : part[t - 1];
    for (int i = 0; i < CH; i++) {
        const int idx = base + i;
        if (idx < NN) { g_off[idx] = run; run += g_deg[idx]; }
    }
}
__global__ __launch_bounds__(256) void fill_kernel(const int* __restrict__ ei)
{
    const int i = blockIdx.x * blockDim.x + threadIdx.x;
    if (i >= EE) return;
    const int dst = ei[EE + i];
    const int pos = atomicAdd(&g_cur[dst], 1);
    g_csr[g_off[dst] + pos] = ei[i];
}

// ---------------------------------------------------------------------------
// Merged 4-in-1 TF32 GEMM: grid (391, 4), blockIdx.y = mode.
//   mode 0: [x|h]  @ WB0 -> rh (tf32 bits) + release flag[bx]
//   mode 1: [x|h]  @ WB1 -> z
//   mode 2: [x|rh] @ WB2 -> y (bf16)   (acquire flag[bx] before K-chunk 8)
//   mode 3: [x|rh] @ WB3 -> w          (acquire flag[bx] before K-chunk 8)
// Safe: CTA dispatch is monotonic in linear id; consumer (782+bx / 1173+bx)
// starts long after producer (bx) finished. Consumers overlap their x-half
// (chunks 0-7) with any residual skew.
// Mainloop = champion shape (BM=128 BN=128 BK=16, 8 warps 64x32, 3-stage).
// ---------------------------------------------------------------------------
#define AP 20
#define BP 20
#define ST 3

__global__ __launch_bounds__(256, 2) void gemm_all(
    const uint32_t* __restrict__ xp, const uint32_t* __restrict__ hp,
    const float* __restrict__ bias_r, const float* __restrict__ bias_z,
    const float* __restrict__ hprev, int Nrows)
{
    __shared__ uint32_t As[ST][128 * AP];
    __shared__ uint32_t Bs[ST][128 * BP];

    const int mode = blockIdx.y;                     // CTA-uniform
    const uint32_t* A0 = xp;
    const uint32_t* A1 = (mode >= 2) ? (const uint32_t*)g_rh32 : hp;
    const uint32_t* B  = g_WB + (size_t)mode * (KK * DH);

    const int tid  = threadIdx.x;
    const int lane = tid & 31;
    const int wid  = tid >> 5;
    const int row0 = blockIdx.x * 128;
    const int wm   = (wid >> 2) * 64;
    const int wn   = (wid & 3) * 32;
    const int g    = lane >> 2;
    const int t    = lane & 3;

    float acc[4][4][4];
#pragma unroll
    for (int mi = 0; mi < 4; mi++)
#pragma unroll
        for (int ni = 0; ni < 4; ni++)
#pragma unroll
            for (int q = 0; q < 4; q++) acc[mi][ni][q] = 0.0f;

    auto stage = [&](int c, int buf) {
        const int k0 = c * 16;
        const uint32_t* Asrc = (k0 < 128) ? A0 : A1;
        const int ka = k0 & 127;
#pragma unroll
        for (int i = 0; i < 2; i++) {      // A: 128 rows x 16 words
            const int id  = tid + i * 256;
            const int row = id >> 2;
            const int kq  = (id & 3) * 4;
            const uint32_t dst = (uint32_t)__cvta_generic_to_shared(
                &As[buf][row * AP + kq]);
            const int sz = (row0 + row < Nrows) ? 16 : 0;
            cpasync16(dst, &Asrc[(size_t)(row0 + row) * DH + ka + kq], sz);
        }
#pragma unroll
        for (int i = 0; i < 2; i++) {      // B: 128 n x 16 words
            const int id = tid + i * 256;
            const int n  = id >> 2;
            const int kq = (id & 3) * 4;
            const uint32_t dst = (uint32_t)__cvta_generic_to_shared(
                &Bs[buf][n * BP + kq]);
            cpasync16(dst, &B[(size_t)n * KK + k0 + kq], 16);
        }
        asm volatile("cp.async.commit_group;");
    };

    stage(0, 0);
    stage(1, 1);

#pragma unroll 1
    for (int c = 0; c < 16; c++) {
        if (c < 15) { asm volatile("cp.async.wait_group 1;"); }
        else        { asm volatile("cp.async.wait_group 0;"); }
        __syncthreads();   // also fences: chunk c-1 reads done -> buf (c+2)%ST free

        // rh dependency: modes 2/3 must not stage K-chunk 8 (first rh chunk)
        // until producer (mode 0, same bx) released the flag.
        if (mode >= 2 && c == 6) {
            if (tid == 0) {
                int v;
                do {
                    asm volatile("ld.global.acquire.gpu.b32 %0, [%1];"
                                 : "=r"(v) : "l"(&g_flag[blockIdx.x]));
                } while (v == 0);
            }
            __syncthreads();
        }

        if (c + 2 < 16) stage(c + 2, (c + 2) % ST);

        const int buf = c % ST;
#pragma unroll
        for (int k8 = 0; k8 < 2; k8++) {
            const int kk = k8 * 8;
            uint32_t a[4][4], b[4][2];
#pragma unroll
            for (int mi = 0; mi < 4; mi++) {
                const int rb = wm + mi * 16 + g;
                a[mi][0] = As[buf][(rb)     * AP + kk + t];
                a[mi][1] = As[buf][(rb + 8) * AP + kk + t];
                a[mi][2] = As[buf][(rb)     * AP + kk + t + 4];
                a[mi][3] = As[buf][(rb + 8) * AP + kk + t + 4];
            }
#pragma unroll
            for (int ni = 0; ni < 4; ni++) {
                const int cb = wn + ni * 8 + g;
                b[ni][0] = Bs[buf][cb * BP + kk + t];
                b[ni][1] = Bs[buf][cb * BP + kk + t + 4];
            }
#pragma unroll
            for (int mi = 0; mi < 4; mi++)
#pragma unroll
                for (int ni = 0; ni < 4; ni++)
                    mma_tf32(acc[mi][ni], a[mi][0], a[mi][1], a[mi][2], a[mi][3],
                             b[ni][0], b[ni][1]);
        }
    }

    // epilogue: thread owns (row = wm+mi*16+g(+8), cols = wn+ni*8+2t, +1)
#pragma unroll
    for (int mi = 0; mi < 4; mi++) {
#pragma unroll
        for (int half = 0; half < 2; half++) {
            const int grow = row0 + wm + mi * 16 + g + half * 8;
            if (grow >= Nrows) continue;
#pragma unroll
            for (int ni = 0; ni < 4; ni++) {
                const int col = wn + ni * 8 + 2 * t;
                float c0 = acc[mi][ni][half * 2 + 0];
                float c1 = acc[mi][ni][half * 2 + 1];
                const size_t off = (size_t)grow * DH + col;
                if (mode == 0) {
                    c0 = sigmoidf_(c0 + bias_r[col]);
                    c1 = sigmoidf_(c1 + bias_r[col + 1]);
                    const float2 hh = *(const float2*)&hprev[off];
                    uint2 o;
                    o.x = f2tf32(c0 * hh.x);
                    o.y = f2tf32(c1 * hh.y);
                    *(uint2*)&g_rh32[off] = o;
                } else if (mode == 1) {
                    float2 o;
                    o.x = sigmoidf_(c0 + bias_z[col]);
                    o.y = sigmoidf_(c1 + bias_z[col + 1]);
                    *(float2*)&g_z[off] = o;
                } else if (mode == 2) {
                    __nv_bfloat162 p;
                    p.x = __float2bfloat16_rn(c0);
                    p.y = __float2bfloat16_rn(c1);
                    *(__nv_bfloat162*)&g_ybf[off] = p;
                } else {
                    *(float2*)&g_w[off] = make_float2(c0, c1);
                }
            }
        }
    }

    // producer: publish rh rows for this bx (release after all block stores)
    if (mode == 0) {
        __syncthreads();
        if (tid == 0) {
            asm volatile("st.global.release.gpu.b32 [%0], %1;"
                         :: "l"(&g_flag[blockIdx.x]), "r"(1));
        }
    }
}

// ---------------------------------------------------------------------------
// Gather + final fused: one warp per node; y rows are bf16 (8B per lane).
// out = (1-z) * (sum_nbr(y)/max(deg,1) + b_l + w) + z * h_prev
// ---------------------------------------------------------------------------
__global__ __launch_bounds__(256) void gather_final(
    const float* __restrict__ hprev, const float* __restrict__ b_l,
    float* __restrict__ out)
{
    const int node = (blockIdx.x * blockDim.x + threadIdx.x) >> 5;
    const int lane = threadIdx.x & 31;
    if (node >= NN) return;

    const int off = g_off[node];
    const int deg = g_deg[node];

    float4 acc = make_float4(0.f, 0.f, 0.f, 0.f);
    auto addrow = [&](int s) {
        const uint2 v = *(const uint2*)&g_ybf[(size_t)s * DH + lane * 4];
        const float2 p0 = __bfloat1622float2(*(const __nv_bfloat162*)&v.x);
        const float2 p1 = __bfloat1622float2(*(const __nv_bfloat162*)&v.y);
        acc.x += p0.x; acc.y += p0.y; acc.z += p1.x; acc.w += p1.y;
    };

    int e = 0;
    for (; e + 4 <= deg; e += 4) {
        const int s0 = g_csr[off + e + 0];
        const int s1 = g_csr[off + e + 1];
        const int s2 = g_csr[off + e + 2];
        const int s3 = g_csr[off + e + 3];
        addrow(s0); addrow(s1); addrow(s2); addrow(s3);
    }
    for (; e < deg; e++) addrow(g_csr[off + e]);

    const float inv = 1.0f / (float)max(deg, 1);
    const size_t o = (size_t)node * DH + lane * 4;
    const float4 w  = *(const float4*)&g_w[o];
    const float4 z  = *(const float4*)&g_z[o];
    const float4 hh = *(const float4*)&hprev[o];
    const float4 bl = *(const float4*)&b_l[lane * 4];

    float4 r;
    float n;
    n = fmaf(acc.x, inv, bl.x) + w.x; r.x = (1.0f - z.x) * n + z.x * hh.x;
    n = fmaf(acc.y, inv, bl.y) + w.y; r.y = (1.0f - z.y) * n + z.y * hh.y;
    n = fmaf(acc.z, inv, bl.z) + w.z; r.z = (1.0f - z.z) * n + z.z * hh.z;
    n = fmaf(acc.w, inv, bl.w) + w.w; r.w = (1.0f - z.w) * n + z.w * hh.w;
    *(float4*)&out[o] = r;
}

// ---------------------------------------------------------------------------
extern "C" void kernel_launch(void* const* d_in, const int* in_sizes, int n_in,
                              void* d_out, int out_size)
{
    const float* x    = (const float*)d_in[0];
    const int*   ei   = (const int*)  d_in[1];
    const float* h    = (const float*)d_in[2];
    const float* W_xr = (const float*)d_in[3];
    const float* b_xr = (const float*)d_in[4];
    const float* W_hr = (const float*)d_in[5];
    const float* W_xz = (const float*)d_in[6];
    const float* b_xz = (const float*)d_in[7];
    const float* W_hz = (const float*)d_in[8];
    const float* W_l  = (const float*)d_in[9];
    const float* b_l  = (const float*)d_in[10];
    const float* W_r  = (const float*)d_in[11];
    float* out = (float*)d_out;

    const uint32_t* xu = (const uint32_t*)x;
    const uint32_t* hu = (const uint32_t*)h;

    const int gemm_grid = (NN + 127) / 128;   // 391

    // One-time resources (created on the first, non-captured, call)
    static cudaStream_t sC = nullptr;
    static cudaEvent_t evRoot, evC;
    if (!sC) {
        cudaStreamCreateWithFlags(&sC, cudaStreamNonBlocking);
        cudaEventCreateWithFlags(&evRoot, cudaEventDisableTiming);
        cudaEventCreateWithFlags(&evC,    cudaEventDisableTiming);
    }

    // Fork: CSR build hidden on side stream
    cudaEventRecord(evRoot, 0);
    cudaStreamWaitEvent(sC, evRoot, 0);
    zero_dc<<<(NN + 255) / 256, 256, 0, sC>>>();
    hist_kernel<<<(EE + 255) / 256, 256, 0, sC>>>(ei);
    scan_kernel<<<1, 1024, 0, sC>>>();
    fill_kernel<<<(EE + 255) / 256, 256, 0, sC>>>(ei);
    cudaEventRecord(evC, sC);

    // Main stream: prep (also zeroes flags) -> merged 4-in-1 GEMM
    prep_w<<<dim3(8, 4, 4), dim3(32, 8)>>>(W_xr, W_hr, W_xz, W_hz, W_l, W_r);
    gemm_all<<<dim3(gemm_grid, 4), 256>>>(xu, hu, b_xr, b_xz, h, NN);

    // Join CSR, then fused gather + final
    cudaStreamWaitEvent(0, evC, 0);
    gather_final<<<(NN * 32 + 255) / 256, 256>>>(h, b_l, out);
}